// round 1
// baseline (speedup 1.0000x reference)
#include <cuda_runtime.h>
#include <cuda_bf16.h>

// Scratch: one raw per-segment value (already divided by scope). 16384 segments.
#define MAX_SEG 16384
__device__ float g_per_seg[MAX_SEG];

// One CTA per segment, 128 threads, each thread handles seg_len/ (128*4) float4s
// (exactly one float4 for seg_len = 512).
__global__ __launch_bounds__(128) void listnet_seg_kernel(
    const float* __restrict__ mean,
    const float* __restrict__ variance,
    const float* __restrict__ targets,
    const int*   __restrict__ scope,
    int seg_len)
{
    const int seg = blockIdx.x;
    const int tid = threadIdx.x;           // 0..127
    const long long base = (long long)seg * seg_len;

    const float4* __restrict__ m4 = reinterpret_cast<const float4*>(mean + base);
    const float4* __restrict__ v4 = reinterpret_cast<const float4*>(variance + base);
    const float4* __restrict__ t4 = reinterpret_cast<const float4*>(targets + base);

    float s1 = 0.0f;  // sum exp(a),  a = x + 0.5 y
    float s2 = 0.0f;  // sum exp(t)
    float s3 = 0.0f;  // sum exp(t) * b,  b = x - 0.5 y

    const int nvec = seg_len >> 2;         // float4s per segment
    for (int i = tid; i < nvec; i += 128) {
        float4 m = m4[i];
        float4 v = v4[i];
        float4 t = t4[i];

        // element 0
        {
            float h = 0.5f * v.x;
            float a = m.x + h, b = m.x - h;
            float ea = __expf(a), et = __expf(t.x);
            s1 += ea; s2 += et; s3 += et * b;
        }
        // element 1
        {
            float h = 0.5f * v.y;
            float a = m.y + h, b = m.y - h;
            float ea = __expf(a), et = __expf(t.y);
            s1 += ea; s2 += et; s3 += et * b;
        }
        // element 2
        {
            float h = 0.5f * v.z;
            float a = m.z + h, b = m.z - h;
            float ea = __expf(a), et = __expf(t.z);
            s1 += ea; s2 += et; s3 += et * b;
        }
        // element 3
        {
            float h = 0.5f * v.w;
            float a = m.w + h, b = m.w - h;
            float ea = __expf(a), et = __expf(t.w);
            s1 += ea; s2 += et; s3 += et * b;
        }
    }

    // Warp reduction (3 values)
    #pragma unroll
    for (int off = 16; off > 0; off >>= 1) {
        s1 += __shfl_down_sync(0xFFFFFFFFu, s1, off);
        s2 += __shfl_down_sync(0xFFFFFFFFu, s2, off);
        s3 += __shfl_down_sync(0xFFFFFFFFu, s3, off);
    }

    __shared__ float sh1[4], sh2[4], sh3[4];
    const int warp = tid >> 5;
    const int lane = tid & 31;
    if (lane == 0) { sh1[warp] = s1; sh2[warp] = s2; sh3[warp] = s3; }
    __syncthreads();

    if (tid == 0) {
        float S1 = sh1[0] + sh1[1] + sh1[2] + sh1[3];
        float S2 = sh2[0] + sh2[1] + sh2[2] + sh2[3];
        float S3 = sh3[0] + sh3[1] + sh3[2] + sh3[3];
        // per_seg = (log(S1) - S3/S2) / scope[seg]
        float raw = logf(S1) - S3 / S2;
        g_per_seg[seg] = raw / (float)scope[seg];
    }
}

// Single-CTA final reduction: mean over segments.
__global__ __launch_bounds__(512) void listnet_reduce_kernel(
    float* __restrict__ out, int num_seg)
{
    const int tid = threadIdx.x;
    float s = 0.0f;
    for (int i = tid; i < num_seg; i += 512)
        s += g_per_seg[i];

    #pragma unroll
    for (int off = 16; off > 0; off >>= 1)
        s += __shfl_down_sync(0xFFFFFFFFu, s, off);

    __shared__ float sh[16];
    const int warp = tid >> 5;
    const int lane = tid & 31;
    if (lane == 0) sh[warp] = s;
    __syncthreads();

    if (tid == 0) {
        float total = 0.0f;
        #pragma unroll
        for (int w = 0; w < 16; w++) total += sh[w];
        out[0] = total / (float)num_seg;
    }
}

extern "C" void kernel_launch(void* const* d_in, const int* in_sizes, int n_in,
                              void* d_out, int out_size)
{
    // metadata order: mean (N), variance (N), scope (NUM_SEG), targets (N)
    const float* mean     = (const float*)d_in[0];
    const float* variance = (const float*)d_in[1];
    const int*   scope    = (const int*)  d_in[2];
    const float* targets  = (const float*)d_in[3];
    float* out = (float*)d_out;

    const int n       = in_sizes[0];
    const int num_seg = in_sizes[2];
    const int seg_len = n / num_seg;   // 512 for this dataset

    listnet_seg_kernel<<<num_seg, 128>>>(mean, variance, targets, scope, seg_len);
    listnet_reduce_kernel<<<1, 512>>>(out, num_seg);
}